// round 2
// baseline (speedup 1.0000x reference)
#include <cuda_runtime.h>

// Conv2d 3x3, stride 1, pad 1: x[32,64,112,112] (*) w[64,64,3,3] + bias[64]
// Direct tiled conv, fp32 FFMA.
//
// Decomposition:
//   grid  = (49 spatial tiles of 16x16, 2 cout-groups of 32, 32 batch)
//   block = 256 threads; thread computes 2x4 pixels x 4 couts = 32 accumulators
//   lane  = (px_t in 0..3) + 4*(cog in 0..7); warp id -> 2-row strip
//     -> input LDS addresses vary only with px_t  (conflict-free, broadcast over cog)
//     -> weight LDS addresses vary only with cog, row stride 73 words
//        (73*4 % 128 = 36B -> bank 4*cog+.., distinct across cog)  -> conflict-free
//   cin processed in chunks of 8 staged through shared memory with halo.
//   SIN_W padded to 20 so input rows are 16B-aligned -> patch loads become LDS.128.

#define BATCH  32
#define CIN    64
#define COUT   64
#define HH     112
#define WW     112
#define TILE   16
#define CC     8            // cin chunk
#define CO_BLK 32           // couts per block
#define SIN_H  (TILE + 2)   // 18
#define SIN_W  20           // 18 live + 2 pad -> rows 16B-aligned (20 % 4 == 0)
#define WSTR   73           // weight row stride per cout (floats), conflict-free

__global__ __launch_bounds__(256, 2)
void conv3x3_tiled(const float* __restrict__ x,
                   const float* __restrict__ w,
                   const float* __restrict__ bias,
                   float* __restrict__ out)
{
    __shared__ float s_in[CC][SIN_H][SIN_W];   // 8*18*20*4 = 11520 B
    __shared__ float s_w[CO_BLK * WSTR];       // 32*73*4   =  9344 B

    const int tid     = threadIdx.x;
    const int bx      = blockIdx.x;            // 0..48
    const int tile_x0 = (bx % 7) * TILE;
    const int tile_y0 = (bx / 7) * TILE;
    const int co_base = blockIdx.y * CO_BLK;   // 0 or 32
    const int n       = blockIdx.z;

    const int lane = tid & 31;
    const int warp = tid >> 5;                 // 0..7
    const int px_t = lane & 3;                 // 0..3
    const int cog  = lane >> 2;                // 0..7
    const int py   = warp * 2;                 // output row in tile (0,2,..,14)
    const int px   = px_t * 4;                 // output col in tile (0,4,8,12)

    float acc[4][2][4];
    #pragma unroll
    for (int c = 0; c < 4; ++c)
        #pragma unroll
        for (int i = 0; i < 2; ++i)
            #pragma unroll
            for (int j = 0; j < 4; ++j)
                acc[c][i][j] = 0.0f;

    const float* x_n = x + (size_t)n * CIN * HH * WW;

    for (int cb = 0; cb < CIN; cb += CC) {
        // ---- stage input tile (with halo) for CC channels; 18 live cols of 20 ----
        #pragma unroll 4
        for (int idx = tid; idx < CC * SIN_H * 18; idx += 256) {
            int ci  = idx / (SIN_H * 18);
            int rem = idx % (SIN_H * 18);
            int iy  = rem / 18;
            int ix  = rem % 18;
            int gy  = tile_y0 - 1 + iy;
            int gx  = tile_x0 - 1 + ix;
            float v = 0.0f;
            if ((unsigned)gy < (unsigned)HH && (unsigned)gx < (unsigned)WW)
                v = __ldg(&x_n[((cb + ci) * HH + gy) * WW + gx]);
            s_in[ci][iy][ix] = v;
        }
        // ---- stage weights: 32 couts x 8 cins x 9 taps ----
        #pragma unroll 2
        for (int idx = tid; idx < CO_BLK * CC * 9; idx += 256) {
            int co = idx / (CC * 9);
            int r  = idx % (CC * 9);
            s_w[co * WSTR + r] = __ldg(&w[(co_base + co) * (CIN * 9) + cb * 9 + r]);
        }
        __syncthreads();

        #pragma unroll
        for (int ci = 0; ci < CC; ++ci) {
            // 4x6 input patch covering this thread's 2x4 outputs + 3x3 halo.
            // Rows are 16B-aligned at px (multiple of 4 words): float4 + float2 loads.
            float r_[4][6];
            #pragma unroll
            for (int i = 0; i < 4; ++i) {
                const float4 v4 = *reinterpret_cast<const float4*>(&s_in[ci][py + i][px]);
                const float2 v2 = *reinterpret_cast<const float2*>(&s_in[ci][py + i][px + 4]);
                r_[i][0] = v4.x; r_[i][1] = v4.y; r_[i][2] = v4.z; r_[i][3] = v4.w;
                r_[i][4] = v2.x; r_[i][5] = v2.y;
            }

            #pragma unroll
            for (int cc = 0; cc < 4; ++cc) {
                const float* wp = &s_w[(cog * 4 + cc) * WSTR + ci * 9];
                float wr[9];
                #pragma unroll
                for (int t = 0; t < 9; ++t) wr[t] = wp[t];

                #pragma unroll
                for (int ky = 0; ky < 3; ++ky)
                    #pragma unroll
                    for (int kx = 0; kx < 3; ++kx)
                        #pragma unroll
                        for (int i = 0; i < 2; ++i)
                            #pragma unroll
                            for (int j = 0; j < 4; ++j)
                                acc[cc][i][j] += wr[ky * 3 + kx] * r_[i + ky][j + kx];
            }
        }
        __syncthreads();
    }

    // ---- epilogue: add bias, vectorized stores (W=112, offsets multiple of 4) ----
    #pragma unroll
    for (int cc = 0; cc < 4; ++cc) {
        const int co = co_base + cog * 4 + cc;
        const float bv = __ldg(&bias[co]);
        #pragma unroll
        for (int i = 0; i < 2; ++i) {
            const int y = tile_y0 + py + i;
            float4 v;
            v.x = acc[cc][i][0] + bv;
            v.y = acc[cc][i][1] + bv;
            v.z = acc[cc][i][2] + bv;
            v.w = acc[cc][i][3] + bv;
            float* op = out + (((size_t)n * COUT + co) * HH + y) * WW + tile_x0 + px;
            *reinterpret_cast<float4*>(op) = v;
        }
    }
}

extern "C" void kernel_launch(void* const* d_in, const int* in_sizes, int n_in,
                              void* d_out, int out_size)
{
    const float* x    = (const float*)d_in[0];  // [32,64,112,112]
    const float* w    = (const float*)d_in[1];  // [64,64,3,3]
    const float* bias = (const float*)d_in[2];  // [64]
    float* out        = (float*)d_out;          // [32,64,112,112]

    dim3 grid(49, COUT / CO_BLK, BATCH);        // (49, 2, 32) = 3136 blocks
    conv3x3_tiled<<<grid, 256>>>(x, w, bias, out);
}

// round 3
// speedup vs baseline: 1.0703x; 1.0703x over previous
#include <cuda_runtime.h>

// Conv2d 3x3, stride 1, pad 1: x[32,64,112,112] (*) w[64,64,3,3] + bias[64]
// Direct tiled conv, fp32 FFMA. Round-3: vectorized weight LDS + CC=16.
//
//   grid  = (49 spatial tiles of 16x16, 2 cout-groups of 32, 32 batch)
//   block = 256 threads; thread = 2x4 pixels x 4 couts = 32 accumulators
//   lane  = (px_t in 0..3) + 4*(cog in 0..7); warp -> 2-row strip
//   input smem  : [ci][18][20]  -> LDS.128 patch loads, conflict-free over cog
//   weight smem : [r=ci*9+tap][36] (32 couts + 4 pad)
//                 -> per tap one LDS.128 gives 4 couts; chunk id (9r+cog)%8
//                    distinct over cog -> conflict-free
//   cin in 4 chunks of 16 (fewer barriers than CC=8).

#define BATCH  32
#define CIN    64
#define COUT   64
#define HH     112
#define WW     112
#define TILE   16
#define CC     16           // cin chunk
#define CO_BLK 32
#define SIN_H  18
#define SIN_W  20           // 18 live + 2 pad -> rows 16B-aligned
#define WROWS  (CC * 9)     // 144
#define WSTR   36           // 32 couts + 4 pad words

__global__ __launch_bounds__(256, 2)
void conv3x3_tiled(const float* __restrict__ x,
                   const float* __restrict__ w,
                   const float* __restrict__ bias,
                   float* __restrict__ out)
{
    __shared__ float s_in[CC][SIN_H][SIN_W];   // 16*18*20*4 = 23040 B
    __shared__ float s_w[WROWS * WSTR];        // 144*36*4   = 20736 B

    const int tid     = threadIdx.x;
    const int bx      = blockIdx.x;            // 0..48
    const int tile_x0 = (bx % 7) * TILE;
    const int tile_y0 = (bx / 7) * TILE;
    const int co_base = blockIdx.y * CO_BLK;   // 0 or 32
    const int n       = blockIdx.z;

    const int lane = tid & 31;
    const int warp = tid >> 5;                 // 0..7
    const int px_t = lane & 3;                 // 0..3
    const int cog  = lane >> 2;                // 0..7
    const int py   = warp * 2;
    const int px   = px_t * 4;

    float acc[4][2][4];
    #pragma unroll
    for (int c = 0; c < 4; ++c)
        #pragma unroll
        for (int i = 0; i < 2; ++i)
            #pragma unroll
            for (int j = 0; j < 4; ++j)
                acc[c][i][j] = 0.0f;

    const float* x_n = x + (size_t)n * CIN * HH * WW;

    for (int cb = 0; cb < CIN; cb += CC) {
        // ---- stage input (halo) for CC channels: 16*18*18 = 5184 elems ----
        #pragma unroll
        for (int k = 0; k < 21; ++k) {
            int idx = tid + k * 256;
            if (idx < CC * SIN_H * 18) {
                int ci  = idx / (SIN_H * 18);
                int rem = idx % (SIN_H * 18);
                int iy  = rem / 18;
                int ix  = rem % 18;
                int gy  = tile_y0 - 1 + iy;
                int gx  = tile_x0 - 1 + ix;
                float v = 0.0f;
                if ((unsigned)gy < (unsigned)HH && (unsigned)gx < (unsigned)WW)
                    v = __ldg(&x_n[((cb + ci) * HH + gy) * WW + gx]);
                s_in[ci][iy][ix] = v;
            }
        }
        // ---- stage weights transposed: [r][co], 144*32 = 4608 elems (18/thread) ----
        // gmem: OIHW -> (co_base+co)*576 + cb*9 + r  (r = ci*9+tap), coalesced along r
        #pragma unroll
        for (int k = 0; k < 18; ++k) {
            int idx = tid + k * 256;
            int co  = idx / WROWS;
            int r   = idx % WROWS;
            s_w[r * WSTR + co] = __ldg(&w[(co_base + co) * (CIN * 9) + cb * 9 + r]);
        }
        __syncthreads();

        #pragma unroll
        for (int ci = 0; ci < CC; ++ci) {
            // 4x6 input patch: LDS.128 + LDS.64 per row, conflict-free
            float r_[4][6];
            #pragma unroll
            for (int i = 0; i < 4; ++i) {
                const float4 v4 = *reinterpret_cast<const float4*>(&s_in[ci][py + i][px]);
                const float2 v2 = *reinterpret_cast<const float2*>(&s_in[ci][py + i][px + 4]);
                r_[i][0] = v4.x; r_[i][1] = v4.y; r_[i][2] = v4.z; r_[i][3] = v4.w;
                r_[i][4] = v2.x; r_[i][5] = v2.y;
            }

            // per tap: one LDS.128 -> 4 couts; 32 FFMA per load
            #pragma unroll
            for (int ky = 0; ky < 3; ++ky) {
                #pragma unroll
                for (int kx = 0; kx < 3; ++kx) {
                    const int t = ky * 3 + kx;
                    const float4 wv = *reinterpret_cast<const float4*>(
                        &s_w[(ci * 9 + t) * WSTR + cog * 4]);
                    const float wc[4] = {wv.x, wv.y, wv.z, wv.w};
                    #pragma unroll
                    for (int cc = 0; cc < 4; ++cc)
                        #pragma unroll
                        for (int i = 0; i < 2; ++i)
                            #pragma unroll
                            for (int j = 0; j < 4; ++j)
                                acc[cc][i][j] += wc[cc] * r_[i + ky][j + kx];
                }
            }
        }
        __syncthreads();
    }

    // ---- epilogue ----
    #pragma unroll
    for (int cc = 0; cc < 4; ++cc) {
        const int co = co_base + cog * 4 + cc;
        const float bv = __ldg(&bias[co]);
        #pragma unroll
        for (int i = 0; i < 2; ++i) {
            const int y = tile_y0 + py + i;
            float4 v;
            v.x = acc[cc][i][0] + bv;
            v.y = acc[cc][i][1] + bv;
            v.z = acc[cc][i][2] + bv;
            v.w = acc[cc][i][3] + bv;
            float* op = out + (((size_t)n * COUT + co) * HH + y) * WW + tile_x0 + px;
            *reinterpret_cast<float4*>(op) = v;
        }
    }
}

extern "C" void kernel_launch(void* const* d_in, const int* in_sizes, int n_in,
                              void* d_out, int out_size)
{
    const float* x    = (const float*)d_in[0];
    const float* w    = (const float*)d_in[1];
    const float* bias = (const float*)d_in[2];
    float* out        = (float*)d_out;

    // Protect 2-CTA occupancy (2 x 43.8 KB smem): prefer max shared carveout.
    static int carveout_set = 0;
    if (!carveout_set) {
        cudaFuncSetAttribute(conv3x3_tiled,
                             cudaFuncAttributePreferredSharedMemoryCarveout, 100);
        carveout_set = 1;
    }

    dim3 grid(49, COUT / CO_BLK, BATCH);
    conv3x3_tiled<<<grid, 256>>>(x, w, bias, out);
}

// round 6
// speedup vs baseline: 2.5358x; 2.3692x over previous
#include <cuda_runtime.h>
#include <cuda_bf16.h>
#include <cstdint>

// ============================================================================
// Conv2d 3x3 s1 p1: x[32,64,112,112] (*) w[64,64,3,3] + bias[64]  (fp32 in/out)
// Implicit GEMM on legacy tensor cores (mma.sync m16n8k16 bf16, fp32 acc),
// 3-term bf16 split: D = xh*wh + xh*wl + xl*wh.  (tcgen05 unavailable: harness
// compiles for compute_100, arch-specific 'a' features rejected by ptxas.)
//
// Tile: 128 pixels (8 rows x 16 cols) x 64 couts x K=576 (9 taps x 64 cin).
// 3136 CTAs x 256 threads (8 warps: 4 m-groups x 2 n-groups, warp = 32px x 32co).
// A = [pixel][ci] bf16 in smem (halo'd 10x18); ldmatrix per-lane addresses do
// the im2col shift per tap. B = [ci][co] bf16 per tap, double-buffered via
// cp.async from pre-converted __device__ scratch. Epilogue: C frags -> smem
// transpose -> coalesced NCHW stores + bias.
// ============================================================================

#define HHH 112
#define WWW 112
#define TRr 8
#define TCc 16
#define HALO_H 10
#define HALO_W 18
#define NPIX  (HALO_H * HALO_W)     // 180
#define PIXSTR 144                  // bytes per pixel row: 64 ci bf16 (128) + 16 pad
#define WSTRB  144                  // bytes per weight row: 64 co bf16 (128) + 16 pad
#define DSTR   132                  // floats per co row in D staging (128 + 4 pad)

// smem layout (bytes)
#define OFF_XH   0                  // 180 * 144 = 25920
#define OFF_XL   25920              // 25920  (D staging reuses [0 .. 33792) after taps)
#define OFF_W    51840              // 2 bufs x 2 terms x 64 rows x 144B = 36864
#define OFF_BIAS 88704              // 64 floats
#define SMEM_TOTAL 88960
#define WBUF_SZ  18432              // one buffer: 2 terms x 64 x 144
#define WTERM_SZ 9216

// ---- weight scratch (pre-converted bf16 hi/lo), [tap][ci][co] ----
__device__ __nv_bfloat16 g_wh[9][64][64];
__device__ __nv_bfloat16 g_wl[9][64][64];

__global__ void convert_weights(const float* __restrict__ w) {
    int idx = blockIdx.x * 256 + threadIdx.x;       // over 9*64*64 = 36864 (OIHW)
    if (idx < 9 * 64 * 64) {
        int co = idx / 576, rem = idx % 576, ci = rem / 9, t = rem % 9;
        float v = w[idx];
        __nv_bfloat16 h = __float2bfloat16(v);
        __nv_bfloat16 l = __float2bfloat16(v - __bfloat162float(h));
        g_wh[t][ci][co] = h;
        g_wl[t][ci][co] = l;
    }
}

// ---- PTX helpers (baseline sm_80+ features only) ----
__device__ __forceinline__ uint32_t smem_u32(const void* p) {
    uint32_t a;
    asm("{ .reg .u64 t; cvta.to.shared.u64 t, %1; cvt.u32.u64 %0, t; }" : "=r"(a) : "l"(p));
    return a;
}
__device__ __forceinline__ void ldsm_x4(uint32_t* r, uint32_t addr) {
    asm volatile("ldmatrix.sync.aligned.m8n8.x4.shared.b16 {%0,%1,%2,%3}, [%4];"
                 : "=r"(r[0]), "=r"(r[1]), "=r"(r[2]), "=r"(r[3]) : "r"(addr));
}
__device__ __forceinline__ void ldsm_x4_t(uint32_t* r, uint32_t addr) {
    asm volatile("ldmatrix.sync.aligned.m8n8.x4.trans.shared.b16 {%0,%1,%2,%3}, [%4];"
                 : "=r"(r[0]), "=r"(r[1]), "=r"(r[2]), "=r"(r[3]) : "r"(addr));
}
__device__ __forceinline__ void mma_bf16(float* c, const uint32_t* a, const uint32_t* b) {
    asm volatile("mma.sync.aligned.m16n8k16.row.col.f32.bf16.bf16.f32 "
                 "{%0,%1,%2,%3}, {%4,%5,%6,%7}, {%8,%9}, {%0,%1,%2,%3};"
                 : "+f"(c[0]), "+f"(c[1]), "+f"(c[2]), "+f"(c[3])
                 : "r"(a[0]), "r"(a[1]), "r"(a[2]), "r"(a[3]), "r"(b[0]), "r"(b[1]));
}
__device__ __forceinline__ void cp16(uint32_t dst, const void* src) {
    asm volatile("cp.async.cg.shared.global [%0], [%1], 16;" :: "r"(dst), "l"(src));
}
#define CP_COMMIT() asm volatile("cp.async.commit_group;" ::: "memory")
#define CP_WAIT0()  asm volatile("cp.async.wait_group 0;" ::: "memory")

__global__ __launch_bounds__(256, 2)
void conv3x3_mma(const float* __restrict__ x,
                 const float* __restrict__ bias_g,
                 float* __restrict__ out)
{
    extern __shared__ char smem[];
    const uint32_t sb = smem_u32(smem);

    const int tid  = threadIdx.x;
    const int lane = tid & 31;
    const int wrp  = tid >> 5;          // 0..7
    const int mw   = wrp >> 1;          // 0..3  (m-group: 32 pixels)
    const int nw   = wrp & 1;           // 0..1  (n-group: 32 couts)

    // tile decode: 98 tiles/img (14 row-tiles x 7 col-tiles)
    const int tile = blockIdx.x;
    const int n    = tile / 98;
    const int rem  = tile % 98;
    const int ty   = rem / 7;           // 0..13
    const int tx   = rem % 7;           // 0..6
    const int y0   = ty * TRr - 1;
    const int x0   = tx * TCc - 1;

    // ---- weight stage lambda: 1024 x 16B chunks -> buf ----
    auto stage_w = [&](int t, int buf) {
        #pragma unroll
        for (int i = 0; i < 4; ++i) {
            int q    = tid + i * 256;          // 0..1023
            int term = q >> 9;                 // 0..1
            int rr   = (q >> 3) & 63;          // ci row
            int c8   = q & 7;                  // 8-co chunk
            const __nv_bfloat16* src = term ? &g_wl[t][rr][c8 * 8] : &g_wh[t][rr][c8 * 8];
            cp16(sb + OFF_W + buf * WBUF_SZ + term * WTERM_SZ + rr * WSTRB + c8 * 16, src);
        }
        CP_COMMIT();
    };

    stage_w(0, 0);   // prefetch tap 0; overlaps x staging below

    if (tid < 64)
        reinterpret_cast<float*>(smem + OFF_BIAS)[tid] = __ldg(&bias_g[tid]);

    // ---- stage x tile: 64 ci x (10x18) halo, fp32 -> bf16 hi/lo ----
    const float* x_n = x + (size_t)n * 64 * HHH * WWW;
    #pragma unroll 5
    for (int k = 0; k < 45; ++k) {
        int idx = tid + k * 256;        // 0..11519 (ci-major)
        int ci  = idx / NPIX;
        int p   = idx % NPIX;
        int rr  = p / HALO_W;
        int cc  = p % HALO_W;
        int gy  = y0 + rr;
        int gx  = x0 + cc;
        float v = 0.0f;
        if ((unsigned)gy < (unsigned)HHH && (unsigned)gx < (unsigned)WWW)
            v = __ldg(&x_n[(ci * HHH + gy) * WWW + gx]);
        __nv_bfloat16 h = __float2bfloat16(v);
        __nv_bfloat16 l = __float2bfloat16(v - __bfloat162float(h));
        *reinterpret_cast<__nv_bfloat16*>(smem + OFF_XH + p * PIXSTR + ci * 2) = h;
        *reinterpret_cast<__nv_bfloat16*>(smem + OFF_XL + p * PIXSTR + ci * 2) = l;
    }

    // ---- per-lane ldmatrix address components ----
    // A: matrix row = ((lane>>3)&1)*8 + (lane&7) == pixel x in tile; y = 2*mw + mi
    const int arow   = ((lane >> 3) & 1) * 8 + (lane & 7);     // 0..15
    const int akoff  = (lane >> 4) * 16;                       // +16B for k-hi lanes
    uint32_t a_base[2][2];
    #pragma unroll
    for (int term = 0; term < 2; ++term)
        #pragma unroll
        for (int mi = 0; mi < 2; ++mi)
            a_base[term][mi] = sb + (term ? OFF_XL : OFF_XH)
                             + ((2 * mw + mi) * HALO_W + arow) * PIXSTR + akoff;
    // B: row = ci = k*16 + ((lane>>3)&1)*8 + (lane&7); col byte = co*2
    const uint32_t b_lane = arow * WSTRB + (lane >> 4) * 16;
    uint32_t b_base[2][2];                                     // [term][co-pair]
    #pragma unroll
    for (int term = 0; term < 2; ++term)
        #pragma unroll
        for (int pr = 0; pr < 2; ++pr)
            b_base[term][pr] = sb + OFF_W + term * WTERM_SZ
                             + nw * 64 + pr * 32 + b_lane;

    float C[2][4][4];
    #pragma unroll
    for (int mi = 0; mi < 2; ++mi)
        #pragma unroll
        for (int ni = 0; ni < 4; ++ni)
            #pragma unroll
            for (int e = 0; e < 4; ++e)
                C[mi][ni][e] = 0.0f;

    // ---- 9 taps ----
    #pragma unroll 1
    for (int t = 0; t < 9; ++t) {
        const int ky  = t / 3;
        const int kx  = t % 3;
        const int buf = t & 1;

        CP_WAIT0();          // tap t weights arrived
        __syncthreads();     // weights + x tile visible; prev buf free
        if (t < 8) stage_w(t + 1, buf ^ 1);   // overlaps compute of tap t

        const uint32_t a_shift = (uint32_t)((ky * HALO_W + kx) * PIXSTR);
        const uint32_t wb      = (uint32_t)(buf * WBUF_SZ);

        #pragma unroll
        for (int k = 0; k < 4; ++k) {
            uint32_t ah[2][4], al[2][4];
            #pragma unroll
            for (int mi = 0; mi < 2; ++mi) {
                ldsm_x4(ah[mi], a_base[0][mi] + a_shift + k * 32);
                ldsm_x4(al[mi], a_base[1][mi] + a_shift + k * 32);
            }
            uint32_t bh[8], bl[8];      // 4 n-chunks x 2 regs
            ldsm_x4_t(bh + 0, b_base[0][0] + wb + k * 16 * WSTRB);
            ldsm_x4_t(bh + 4, b_base[0][1] + wb + k * 16 * WSTRB);
            ldsm_x4_t(bl + 0, b_base[1][0] + wb + k * 16 * WSTRB);
            ldsm_x4_t(bl + 4, b_base[1][1] + wb + k * 16 * WSTRB);

            #pragma unroll
            for (int ni = 0; ni < 4; ++ni) {
                #pragma unroll
                for (int mi = 0; mi < 2; ++mi) {
                    mma_bf16(C[mi][ni], ah[mi], bh + ni * 2);
                    mma_bf16(C[mi][ni], ah[mi], bl + ni * 2);
                    mma_bf16(C[mi][ni], al[mi], bh + ni * 2);
                }
            }
        }
    }

    // ---- epilogue: C frags -> smem [co][pix] (reuses x region) -> coalesced ----
    __syncthreads();         // all warps done reading s_x
    float* s_d = reinterpret_cast<float*>(smem);            // 64 x DSTR floats
    {
        const int rbase = mw * 32 + (lane >> 2);            // pixel of d0/d1
        const int cbase = nw * 32 + (lane & 3) * 2;         // cout of d0
        #pragma unroll
        for (int mi = 0; mi < 2; ++mi)
            #pragma unroll
            for (int ni = 0; ni < 4; ++ni) {
                const int m = rbase + mi * 16;
                const int c = cbase + ni * 8;
                s_d[(c    ) * DSTR + m    ] = C[mi][ni][0];
                s_d[(c + 1) * DSTR + m    ] = C[mi][ni][1];
                s_d[(c    ) * DSTR + m + 8] = C[mi][ni][2];
                s_d[(c + 1) * DSTR + m + 8] = C[mi][ni][3];
            }
    }
    __syncthreads();
    const float* s_bias = reinterpret_cast<const float*>(smem + OFF_BIAS);
    #pragma unroll 8
    for (int i = 0; i < 32; ++i) {
        int idx = tid + i * 256;        // 0..8191
        int co  = idx >> 7;
        int p   = idx & 127;
        int oy  = ty * TRr + (p >> 4);
        int ox  = tx * TCc + (p & 15);
        out[(((size_t)n * 64 + co) * HHH + oy) * WWW + ox] = s_d[co * DSTR + p] + s_bias[co];
    }
}

extern "C" void kernel_launch(void* const* d_in, const int* in_sizes, int n_in,
                              void* d_out, int out_size)
{
    const float* x    = (const float*)d_in[0];
    const float* w    = (const float*)d_in[1];
    const float* bias = (const float*)d_in[2];
    float* out        = (float*)d_out;

    convert_weights<<<144, 256>>>(w);

    cudaFuncSetAttribute(conv3x3_mma,
                         cudaFuncAttributeMaxDynamicSharedMemorySize, SMEM_TOTAL);
    conv3x3_mma<<<3136, 256, SMEM_TOTAL>>>(x, bias, out);
}